// round 1
// baseline (speedup 1.0000x reference)
#include <cuda_runtime.h>
#include <cuda_bf16.h>

// NBVLoss: weighted BCE reduction.
//   out = 10 * sum_{t==1} -max(log(p), -100)  +  1 * sum_{t==0} -max(log1p(-p), -100)
// Streaming reduction over 2 x 134M floats -> HBM-bound (~1.07 GB read).

static __device__ __forceinline__ float bce_contrib(float p, float t) {
    // target is exactly 0.0f or 1.0f
    bool is_one = (t != 0.0f);
    float l = is_one ? __logf(p) : log1pf(-p);
    // __logf max rel error ~2^-21 on values of magnitude <=13.8 -> absolute error
    // ~7e-6 per element, random-sign across 1.3e8 elements -> far below 1e-3 rel.
    l = fmaxf(l, -100.0f);
    return is_one ? (-10.0f * l) : (-l);
}

__global__ void __launch_bounds__(256)
nbv_loss_kernel(const float4* __restrict__ pred,
                const float4* __restrict__ targ,
                float* __restrict__ out,
                int n4) {
    float acc = 0.0f;
    int stride = gridDim.x * blockDim.x;
    for (int i = blockIdx.x * blockDim.x + threadIdx.x; i < n4; i += stride) {
        float4 pv = pred[i];
        float4 tv = targ[i];
        acc += bce_contrib(pv.x, tv.x);
        acc += bce_contrib(pv.y, tv.y);
        acc += bce_contrib(pv.z, tv.z);
        acc += bce_contrib(pv.w, tv.w);
    }

    // warp reduction
    #pragma unroll
    for (int off = 16; off > 0; off >>= 1)
        acc += __shfl_xor_sync(0xFFFFFFFFu, acc, off);

    __shared__ float warp_sums[8];
    int lane = threadIdx.x & 31;
    int wid  = threadIdx.x >> 5;
    if (lane == 0) warp_sums[wid] = acc;
    __syncthreads();

    if (wid == 0) {
        float v = (lane < 8) ? warp_sums[lane] : 0.0f;
        #pragma unroll
        for (int off = 4; off > 0; off >>= 1)
            v += __shfl_xor_sync(0xFFFFFFFFu, v, off);
        if (lane == 0)
            atomicAdd(out, v);
    }
}

extern "C" void kernel_launch(void* const* d_in, const int* in_sizes, int n_in,
                              void* d_out, int out_size) {
    const float4* pred = (const float4*)d_in[0];
    const float4* targ = (const float4*)d_in[1];
    float* out = (float*)d_out;

    int n = in_sizes[0];           // 134217728, divisible by 4
    int n4 = n >> 2;               // 33554432 float4 elements

    // d_out is poisoned 0xAA -> zero it (memset nodes are graph-capturable)
    cudaMemsetAsync(out, 0, sizeof(float));

    const int threads = 256;
    const int blocks = 148 * 32;   // 4736 blocks, grid-stride (~28 float4/thread)
    nbv_loss_kernel<<<blocks, threads>>>(pred, targ, out, n4);
}

// round 2
// speedup vs baseline: 1.9546x; 1.9546x over previous
#include <cuda_runtime.h>
#include <cuda_bf16.h>

// NBVLoss: weighted BCE reduction.
//   out = 10 * sum_{t==1} -max(log(p), -100)  +  1 * sum_{t==0} -max(log(1-p), -100)
// target is exactly 0/1, so only ONE log is needed per element:
//   x = t ? p : (1-p);  l = max(log(x), -100);  contribution = -(t ? 10 : 1) * l
// log1p(-p) -> __logf(1-p) is safe here: p >= 1e-6, so |err(1-p)| <= 1.2e-7
// per elem -> <= ~8 absolute over the whole sum (~7.4e8) -> ~1e-8 relative.
// Per element: 1 MUFU.LG2 + ~6 fixed-lat ops -> fully hidden under HBM stream.

static __device__ __forceinline__ float bce_contrib(float p, float t) {
    bool is_one = (t != 0.0f);
    float x = is_one ? p : (1.0f - p);
    float l = __logf(x);              // MUFU.LG2 + FMUL(ln2)
    l = fmaxf(l, -100.0f);            // never binds (|l| <= 13.9), 1 FMNMX
    float w = is_one ? 10.0f : 1.0f;  // FSEL
    return -w * l;
}

__global__ void __launch_bounds__(256)
nbv_loss_kernel(const float4* __restrict__ pred,
                const float4* __restrict__ targ,
                float* __restrict__ out,
                int n4) {
    float acc = 0.0f;
    int stride = gridDim.x * blockDim.x;
    for (int i = blockIdx.x * blockDim.x + threadIdx.x; i < n4; i += stride) {
        float4 pv = pred[i];
        float4 tv = targ[i];
        acc += bce_contrib(pv.x, tv.x);
        acc += bce_contrib(pv.y, tv.y);
        acc += bce_contrib(pv.z, tv.z);
        acc += bce_contrib(pv.w, tv.w);
    }

    // warp reduction
    #pragma unroll
    for (int off = 16; off > 0; off >>= 1)
        acc += __shfl_xor_sync(0xFFFFFFFFu, acc, off);

    __shared__ float warp_sums[8];
    int lane = threadIdx.x & 31;
    int wid  = threadIdx.x >> 5;
    if (lane == 0) warp_sums[wid] = acc;
    __syncthreads();

    if (wid == 0) {
        float v = (lane < 8) ? warp_sums[lane] : 0.0f;
        #pragma unroll
        for (int off = 4; off > 0; off >>= 1)
            v += __shfl_xor_sync(0xFFFFFFFFu, v, off);
        if (lane == 0)
            atomicAdd(out, v);
    }
}

extern "C" void kernel_launch(void* const* d_in, const int* in_sizes, int n_in,
                              void* d_out, int out_size) {
    const float4* pred = (const float4*)d_in[0];
    const float4* targ = (const float4*)d_in[1];
    float* out = (float*)d_out;

    int n = in_sizes[0];           // 134217728, divisible by 4
    int n4 = n >> 2;               // 33554432 float4 elements

    // d_out is poisoned 0xAA -> zero it (memset nodes are graph-capturable)
    cudaMemsetAsync(out, 0, sizeof(float));

    const int threads = 256;
    const int blocks = 148 * 32;   // 4736 blocks, grid-stride (~28 float4/thread)
    nbv_loss_kernel<<<blocks, threads>>>(pred, targ, out, n4);
}